// round 17
// baseline (speedup 1.0000x reference)
#include <cuda_runtime.h>
#include <cuda_bf16.h>
#include <cstdint>

// BasicMFNet: embed_user [8192,64] f32, embed_item [16384,64] f32,
// indices [2,200000] (int32 or int64 — detected at runtime), ratings [200000] f32.
// Output: pred [U*I] | label [U*I] | ratio (1)  -- all float32.
constexpr int U = 8192;
constexpr int I = 16384;
constexpr int H = 64;

constexpr int TILE = 128;        // M and N tile
constexpr int NCOLF = I / TILE;  // 128 column-tile flags
constexpr int NROWF = U / TILE;  // 64 row-tile flags

// Device scratch (no allocations). Zero at module load; k_scatter re-zeroes
// masks/flags at the end of every launch, so each launch starts clean
// (deterministic across graph replays). g_idx_is_i32 is rewritten by
// k_detect at the start of every launch.
__device__ int g_umask[U];
__device__ int g_imask[I];
__device__ int g_colflag[NCOLF];
__device__ int g_rowflag[NROWF];
__device__ int g_idx_is_i32;

// ---------------------------------------------------------------------------
// Packed f32x2 helpers (Blackwell FFMA2 — PTX-only path, 2x fp32 FMA rate)
// ---------------------------------------------------------------------------
__device__ __forceinline__ unsigned long long dup_f32(float x) {
    unsigned long long r;
    unsigned xi = __float_as_uint(x);
    asm("mov.b64 %0, {%1, %1};" : "=l"(r) : "r"(xi));
    return r;
}
__device__ __forceinline__ void ffma2(unsigned long long& d,
                                      unsigned long long a,
                                      unsigned long long b) {
    asm("fma.rn.f32x2 %0, %1, %2, %0;" : "+l"(d) : "l"(a), "l"(b));
}

__device__ __forceinline__ void read_uv_d(const void* idx, int nnz, int t,
                                          int is_i32, int& u, int& v) {
    if (is_i32) {
        const int* p = (const int*)idx;
        u = p[t]; v = p[nnz + t];
    } else {
        const long long* p = (const long long*)idx;
        u = (int)p[t]; v = (int)p[nnz + t];
    }
}

// ---------------------------------------------------------------------------
// Kernel 0: detect index dtype ONCE (1 block) + write ratio output.
// int64 values < 2^31 have every odd int32 word == 0; genuine int32 index
// data can't have 2048 zero odd words. Runs in ~3us; every consumer then
// reads g_idx_is_i32 with a single uniform load (the per-block detect scan
// in R16 cost 42.6us across 782 blocks — this removes it).
// ---------------------------------------------------------------------------
__global__ void k_detect(const int* __restrict__ idx_w32, int nnz,
                         float* __restrict__ out, long long out_size) {
    __shared__ int s_found;
    if (threadIdx.x == 0) s_found = 0;
    __syncthreads();
    int found = 0;
    for (int i = 2 * (int)threadIdx.x + 1; i < 4096; i += 2 * (int)blockDim.x)
        if (idx_w32[i] != 0) found = 1;
    if (found) s_found = 1;
    __syncthreads();
    if (threadIdx.x == 0) {
        g_idx_is_i32 = s_found;
        if (out_size > 2ll * U * I)
            out[2ull * U * I] = (float)(((double)U * (double)I) / (double)nnz);
    }
}

// ---------------------------------------------------------------------------
// Kernel 1: set masks + tile flags (4 entries/thread, bounds-guarded).
// Masks/flags were zeroed by the previous launch's scatter (or static init
// on the first run).
// ---------------------------------------------------------------------------
__global__ void k_set_masks(const void* __restrict__ idx, int nnz) {
    const int is_i32 = g_idx_is_i32;
    int base = (blockIdx.x * blockDim.x + threadIdx.x) * 4;
    #pragma unroll
    for (int j = 0; j < 4; j++) {
        int t = base + j;
        if (t >= nnz) break;
        int u, v;
        read_uv_d(idx, nnz, t, is_i32, u, v);
        if (u >= 0 && u < U) { g_umask[u] = 1; g_rowflag[u >> 7] = 1; }
        if (v >= 0 && v < I) { g_imask[v] = 1; g_colflag[v >> 7] = 1; }
    }
}

// ---------------------------------------------------------------------------
// Kernel 2: GEMM  pred = (masked eu) * (masked ei)^T.
// R7's 264us GEMM (128x128 tile, 256 threads, 8x8 microtile split
// (4+4)x(4+4) at stride 64, whole H=64 in smem, single sync) with masks
// applied during the smem load phase (validated R16: no GEMM regression).
// Epilogue zero-fills the matching label tile (fused with pred stores).
// ---------------------------------------------------------------------------
__global__ void __launch_bounds__(256, 2) k_gemm(const float* __restrict__ eu,
                                                 const float* __restrict__ ei,
                                                 float* __restrict__ out) {
    const int bx = blockIdx.x;            // column tile (items)
    const int by = blockIdx.y;            // row tile (users)
    const int m0 = by * TILE;
    const int n0 = bx * TILE;
    const int tid = threadIdx.x;
    const int tm4a = (tid >> 4) * 4;      // 16 row-groups of 4
    const int tn4a = (tid & 15) * 4;      // 16 col-groups of 4 (consecutive 16B)

    float* pred  = out;
    float* label = out + (size_t)U * I;

    const bool active = (g_rowflag[by] != 0) && (g_colflag[bx] != 0);

    if (!active) {
        const ulonglong2 z = make_ulonglong2(0ull, 0ull);
        #pragma unroll
        for (int i = 0; i < 8; i++) {
            int row = m0 + (i < 4 ? tm4a + i : 64 + tm4a + (i - 4));
            size_t off = (size_t)row * I + n0 + tn4a;
            *reinterpret_cast<ulonglong2*>(pred + off)       = z;
            *reinterpret_cast<ulonglong2*>(pred + off + 64)  = z;
            *reinterpret_cast<ulonglong2*>(label + off)      = z;
            *reinterpret_cast<ulonglong2*>(label + off + 64) = z;
        }
        return;
    }

    __shared__ float As[H][TILE];   // k-major (transposed) tiles, 32 KB each
    __shared__ float Bs[H][TILE];

    // Single load phase: 128 rows x 64 k per tile; lanes stride rows ->
    // conflict-free STS.32 (bank = r). Mask applied as a float multiply.
    #pragma unroll
    for (int it = 0; it < 8; it++) {
        int id = tid + it * 256;          // 0..2047
        int r = id & 127;
        int c = id >> 7;                  // 0..15 (k-group of 4)
        float4 va = *reinterpret_cast<const float4*>(
            &eu[(size_t)(m0 + r) * H + c * 4]);
        float um = g_umask[m0 + r] ? 1.0f : 0.0f;
        As[c * 4 + 0][r] = va.x * um;
        As[c * 4 + 1][r] = va.y * um;
        As[c * 4 + 2][r] = va.z * um;
        As[c * 4 + 3][r] = va.w * um;
        float4 vb = *reinterpret_cast<const float4*>(
            &ei[(size_t)(n0 + r) * H + c * 4]);
        float im = g_imask[n0 + r] ? 1.0f : 0.0f;
        Bs[c * 4 + 0][r] = vb.x * im;
        Bs[c * 4 + 1][r] = vb.y * im;
        Bs[c * 4 + 2][r] = vb.z * im;
        Bs[c * 4 + 3][r] = vb.w * im;
    }

    unsigned long long acc[8][4];    // [row][col-pair]
    #pragma unroll
    for (int i = 0; i < 8; i++)
        #pragma unroll
        for (int j = 0; j < 4; j++) acc[i][j] = 0ull;

    __syncthreads();

    #pragma unroll 8
    for (int k = 0; k < H; k++) {
        // A: 16B broadcast loads (2 distinct addrs/warp -> ~free)
        float4 a0 = *reinterpret_cast<const float4*>(&As[k][tm4a]);
        float4 a1 = *reinterpret_cast<const float4*>(&As[k][tm4a + 64]);
        // B: lanes 0-15 read consecutive 16B chunks (bytes 0..255) ->
        // conflict-free; lanes 16-31 broadcast the same addrs.
        ulonglong2 b0 = *reinterpret_cast<const ulonglong2*>(&Bs[k][tn4a]);
        ulonglong2 b1 = *reinterpret_cast<const ulonglong2*>(&Bs[k][tn4a + 64]);
        unsigned long long bp0 = b0.x, bp1 = b0.y, bp2 = b1.x, bp3 = b1.y;
        float av[8] = {a0.x, a0.y, a0.z, a0.w, a1.x, a1.y, a1.z, a1.w};
        #pragma unroll
        for (int i = 0; i < 8; i++) {
            unsigned long long ad = dup_f32(av[i]);
            ffma2(acc[i][0], ad, bp0);
            ffma2(acc[i][1], ad, bp1);
            ffma2(acc[i][2], ad, bp2);
            ffma2(acc[i][3], ad, bp3);
        }
    }

    // Epilogue: store pred tile + zero label tile. Lanes 0-15 of a warp cover
    // 256 consecutive bytes per row-chunk -> fully coalesced STG.128.
    const ulonglong2 z = make_ulonglong2(0ull, 0ull);
    #pragma unroll
    for (int i = 0; i < 8; i++) {
        int row = m0 + (i < 4 ? tm4a + i : 64 + tm4a + (i - 4));
        size_t off = (size_t)row * I + n0 + tn4a;
        *reinterpret_cast<ulonglong2*>(pred + off) =
            make_ulonglong2(acc[i][0], acc[i][1]);
        *reinterpret_cast<ulonglong2*>(pred + off + 64) =
            make_ulonglong2(acc[i][2], acc[i][3]);
        *reinterpret_cast<ulonglong2*>(label + off)      = z;
        *reinterpret_cast<ulonglong2*>(label + off + 64) = z;
    }
}

// ---------------------------------------------------------------------------
// Kernel 3: scatter-add ratings into label (4 entries/thread — measured
// faster than 1/thread: 11.4us vs 15us) + re-zero masks/flags for the next
// launch (scatter never reads masks; the GEMM has already consumed them).
// ---------------------------------------------------------------------------
__global__ void k_scatter(const void* __restrict__ idx,
                          const float* __restrict__ ratings,
                          float* __restrict__ out, int nnz) {
    const int is_i32 = g_idx_is_i32;
    float* label = out + (size_t)U * I;
    int gtid = blockIdx.x * blockDim.x + threadIdx.x;
    int base = gtid * 4;
    #pragma unroll
    for (int j = 0; j < 4; j++) {
        int t = base + j;
        if (t >= nnz) break;
        int u, v;
        read_uv_d(idx, nnz, t, is_i32, u, v);
        if (u < 0 || u >= U || v < 0 || v >= I) continue;
        atomicAdd(&label[(size_t)u * I + v], ratings[t]);
    }
    // Cleanup for next launch (24768 words total; grid has ~50k threads).
    if (gtid < U) g_umask[gtid] = 0;
    if (gtid < I) g_imask[gtid] = 0;
    if (gtid < NCOLF) g_colflag[gtid] = 0;
    if (gtid < NROWF) g_rowflag[gtid] = 0;
}

// ---------------------------------------------------------------------------
extern "C" void kernel_launch(void* const* d_in, const int* in_sizes, int n_in,
                              void* d_out, int out_size) {
    const float* eu = (const float*)d_in[0];
    const float* ei = (const float*)d_in[1];
    const void*  idx = d_in[2];
    const float* ratings = (const float*)d_in[3];
    float* out = (float*)d_out;
    const int nnz = in_sizes[3];

    // 0. dtype detect (once) + ratio
    k_detect<<<1, 256>>>((const int*)idx, nnz, out, (long long)out_size);
    // 1. masks + flags
    {
        int blocks = (nnz + 1023) / 1024;   // 4 entries/thread
        k_set_masks<<<blocks, 256>>>(idx, nnz);
    }
    // 2. GEMM (masks applied in-load; writes pred + zeros label)
    {
        dim3 grid(I / TILE, U / TILE);
        k_gemm<<<grid, 256>>>(eu, ei, out);
    }
    // 3. scatter ratings + cleanup masks/flags for next launch
    {
        int blocks = (nnz + 1023) / 1024;
        k_scatter<<<blocks, 256>>>(idx, ratings, out, nnz);
    }
}